// round 15
// baseline (speedup 1.0000x reference)
#include <cuda_runtime.h>

// Problem constants
#define B_  256
#define T_  1024
#define I_  3
#define H_  128
#define O_  3

#define TANH_C 2.885390081777927f   // 2*log2(e)

// ---------------------------------------------------------------------------
// Fast tanh with PRE-SCALED argument: caller provides u = 2*log2(e)*x
// (folded into the weights), so the chain is MUFU.EX2 -> FADD -> MUFU.RCP
// -> FFMA, no leading FMUL. Limits exact. Measured end-to-end err ~5e-7.
// ---------------------------------------------------------------------------
__device__ __forceinline__ float fast_tanh_prescaled(float u) {
    float e;
    asm("ex2.approx.f32 %0, %1;" : "=f"(e) : "f"(u));
    float rd;
    asm("rcp.approx.f32 %0, %1;" : "=f"(rd) : "f"(1.0f + e));
    return fmaf(-2.0f, rd, 1.0f);
}

// ---------------------------------------------------------------------------
// Recurrent kernel (399us winner) with weights pre-scaled by 2*log2(e).
// One block per batch, one thread per hidden unit, W_hh row in 128 regs,
// double-buffered h in smem, one barrier per step, x prefetch, anti-phase
// skew for second-slot blocks.
// ---------------------------------------------------------------------------
__global__ void __launch_bounds__(H_, 2)
rnn_recurrent_kernel(const float* __restrict__ inputs,   // [B, T, I]
                     const float* __restrict__ W_ih,     // [H, I]
                     const float* __restrict__ W_hh,     // [H, H]
                     const float* __restrict__ b_ih,     // [H]
                     const float* __restrict__ b_hh,     // [H]
                     const float* __restrict__ h0,       // [1, H]
                     float* __restrict__ hiddens)        // [B, T, H]
{
    const int b = blockIdx.x;
    const int j = threadIdx.x;

    __shared__ float hbuf[2][H_];

    // W_hh row j -> registers, pre-scaled by 2*log2(e)
    float w[H_];
    const float4* wrow = reinterpret_cast<const float4*>(W_hh + j * H_);
#pragma unroll
    for (int kk = 0; kk < H_ / 4; ++kk) {
        float4 v = wrow[kk];
        w[4 * kk + 0] = v.x * TANH_C;
        w[4 * kk + 1] = v.y * TANH_C;
        w[4 * kk + 2] = v.z * TANH_C;
        w[4 * kk + 3] = v.w * TANH_C;
    }

    const float wi0  = W_ih[j * I_ + 0] * TANH_C;
    const float wi1  = W_ih[j * I_ + 1] * TANH_C;
    const float wi2  = W_ih[j * I_ + 2] * TANH_C;
    const float bias = (b_ih[j] + b_hh[j]) * TANH_C;

    hbuf[0][j] = h0[j];

    // Anti-phase-lock skew for second-slot blocks (part of the 399us config)
    if (b >= 148) {
        float d = bias * 1e-30f;
#pragma unroll 1
        for (int i = 0; i < 75; ++i)
            d = fmaf(d, 0.999f, 1e-30f);
        if (d > 1e10f) hbuf[0][0] = d;   // never taken
    }
    __syncthreads();

    const float* inb  = inputs + (size_t)b * T_ * I_;
    float*       hout = hiddens + (size_t)b * T_ * H_;

    float x0 = inb[0], x1 = inb[1], x2 = inb[2];

    int cur = 0;
#pragma unroll 1
    for (int t = 0; t < T_; ++t) {
        // Seed chain 0 with the (pre-scaled) input projection
        float a0 = fmaf(x0, wi0, fmaf(x1, wi1, fmaf(x2, wi2, bias)));
        float a1 = 0.f, a2 = 0.f, a3 = 0.f;

        // prefetch next x (off the critical tail)
        {
            const int tn = (t + 1 < T_) ? (t + 1) : (T_ - 1);
            const float* nx = inb + tn * I_;
            x0 = nx[0]; x1 = nx[1]; x2 = nx[2];
        }

        const float4* h4 = reinterpret_cast<const float4*>(hbuf[cur]);
#pragma unroll
        for (int kk = 0; kk < H_ / 4; ++kk) {
            float4 hv = h4[kk];
            a0 = fmaf(hv.x, w[4 * kk + 0], a0);
            a1 = fmaf(hv.y, w[4 * kk + 1], a1);
            a2 = fmaf(hv.z, w[4 * kk + 2], a2);
            a3 = fmaf(hv.w, w[4 * kk + 3], a3);
        }
        const float acc = (a0 + a1) + (a2 + a3);   // = 2*log2(e)*preact

        const float hn = fast_tanh_prescaled(acc);
        const int nxt = cur ^ 1;
        hbuf[nxt][j] = hn;
        hout[t * H_ + j] = hn;
        cur = nxt;
        __syncthreads();
    }
}

// ---------------------------------------------------------------------------
// Output projection, v2:
//  - REVERSED block order: newest-written hiddens rows are read first, so
//    the scan consumes L2 in MRU order instead of thrashing it (128MB data
//    vs 126MB L2: forward scan = ~0% hit, backward scan = ~95% hit).
//  - Half-warp per row: 16 lanes x 8 h-values, width-16 shuffle reduction
//    (4 levels, 2 rows reduced in parallel) -> ~50% fewer instructions than
//    the full-warp variant, so the kernel can actually run at L2 speed.
// Block: 256 threads = 8 warps, each warp does 4 rows -> 32 rows/block.
// ---------------------------------------------------------------------------
#define OP_THREADS 256
#define OP_ROWS_PER_BLOCK 32

__global__ void __launch_bounds__(OP_THREADS)
rnn_outproj_kernel(const float* __restrict__ hiddens, // [B*T, H]
                   const float* __restrict__ W_out,   // [O, H]
                   const float* __restrict__ b_out,   // [O]
                   float* __restrict__ out)           // [B*T, O]
{
    // Reversed launch order: block 0 processes the LAST rows.
    const int rb   = (int)gridDim.x - 1 - (int)blockIdx.x;
    const int warp = threadIdx.x >> 5;
    const int lane = threadIdx.x & 31;
    const int half = lane >> 4;      // 0/1: which row of the pair
    const int sub  = lane & 15;      // position within the 16-lane group

    const size_t row0 = (size_t)rb * OP_ROWS_PER_BLOCK + warp * 4;

    // Each lane covers h[sub*8 .. sub*8+8): 2 float4 of W per output row
    const float4* W0 = reinterpret_cast<const float4*>(W_out + 0 * H_ + sub * 8);
    const float4* W1 = reinterpret_cast<const float4*>(W_out + 1 * H_ + sub * 8);
    const float4* W2 = reinterpret_cast<const float4*>(W_out + 2 * H_ + sub * 8);
    const float4 w0a = W0[0], w0b = W0[1];
    const float4 w1a = W1[0], w1b = W1[1];
    const float4 w2a = W2[0], w2b = W2[1];
    const float bo0 = b_out[0], bo1 = b_out[1], bo2 = b_out[2];

    // Rows: pair p in {0,1}, this lane's row = row0 + 2*p + half.
    // Issue all 4 h loads up front (MLP).
    float4 ha[2], hb[2];
#pragma unroll
    for (int p = 0; p < 2; ++p) {
        const float* hrow = hiddens + (row0 + 2 * p + half) * H_ + sub * 8;
        ha[p] = reinterpret_cast<const float4*>(hrow)[0];
        hb[p] = reinterpret_cast<const float4*>(hrow)[1];
    }

#pragma unroll
    for (int p = 0; p < 2; ++p) {
        float s0 = ha[p].x * w0a.x + ha[p].y * w0a.y + ha[p].z * w0a.z + ha[p].w * w0a.w
                 + hb[p].x * w0b.x + hb[p].y * w0b.y + hb[p].z * w0b.z + hb[p].w * w0b.w;
        float s1 = ha[p].x * w1a.x + ha[p].y * w1a.y + ha[p].z * w1a.z + ha[p].w * w1a.w
                 + hb[p].x * w1b.x + hb[p].y * w1b.y + hb[p].z * w1b.z + hb[p].w * w1b.w;
        float s2 = ha[p].x * w2a.x + ha[p].y * w2a.y + ha[p].z * w2a.z + ha[p].w * w2a.w
                 + hb[p].x * w2b.x + hb[p].y * w2b.y + hb[p].z * w2b.z + hb[p].w * w2b.w;

        // width-16 reduction: both halves reduce their rows in parallel
#pragma unroll
        for (int off = 8; off > 0; off >>= 1) {
            s0 += __shfl_down_sync(0xffffffffu, s0, off, 16);
            s1 += __shfl_down_sync(0xffffffffu, s1, off, 16);
            s2 += __shfl_down_sync(0xffffffffu, s2, off, 16);
        }
        if (sub == 0) {
            float* o = out + (row0 + 2 * p + half) * O_;
            o[0] = s0 + bo0;
            o[1] = s1 + bo1;
            o[2] = s2 + bo2;
        }
    }
}

// ---------------------------------------------------------------------------
// kernel_launch
// ---------------------------------------------------------------------------
extern "C" void kernel_launch(void* const* d_in, const int* in_sizes, int n_in,
                              void* d_out, int out_size)
{
    const float* inputs = (const float*)d_in[0];
    const float* W_ih   = (const float*)d_in[1];
    const float* W_hh   = (const float*)d_in[2];
    const float* b_ih   = (const float*)d_in[3];
    const float* b_hh   = (const float*)d_in[4];
    const float* h0     = (const float*)d_in[5];
    const float* W_out  = (const float*)d_in[6];
    const float* b_out  = (const float*)d_in[7];

    float* out     = (float*)d_out;                        // [B,T,O]
    float* hiddens = (float*)d_out + (size_t)B_ * T_ * O_; // [B,T,H]

    rnn_recurrent_kernel<<<B_, H_>>>(inputs, W_ih, W_hh, b_ih, b_hh, h0, hiddens);

    const int rows   = B_ * T_;                      // 262144
    const int blocks = rows / OP_ROWS_PER_BLOCK;     // 8192 (exact)
    rnn_outproj_kernel<<<blocks, OP_THREADS>>>(hiddens, W_out, b_out, out);
}